// round 12
// baseline (speedup 1.0000x reference)
#include <cuda_runtime.h>
#include <cuda_bf16.h>
#include <cstdint>
#include <cstddef>

// Problem constants
constexpr int B_  = 2;
constexpr int S_  = 2048;
constexpr int D_  = 1024;
constexpr int H_  = 16;
constexpr int HD_ = 64;
constexpr int M_   = B_ * S_;                     // 4096
constexpr int KP_  = 2 * D_;                      // 2048 (hi|lo side by side)

// ---------------------------------------------------------------------------
// Scratch (__device__ globals; no allocation allowed)
// ---------------------------------------------------------------------------
__device__ float g_f32[4 * B_ * S_ * D_];                    // pool: Qbf,Kbf,Vbf,Cbf
__device__ __nv_bfloat16 g_act_bf[4 * (size_t)M_ * KP_];     // qc, kc, vc (gemm-tiled)
__device__ __nv_bfloat16 g_w_bf[4 * (size_t)D_ * KP_];       // weights (gemm-tiled)

// ---------------------------------------------------------------------------
// Helpers (baseline PTX only — sm_90-level, no a-gated instructions)
// ---------------------------------------------------------------------------
__device__ __forceinline__ uint32_t smem_u32(const void* p) {
    uint32_t a;
    asm("{ .reg .u64 t; cvta.to.shared.u64 t, %1; cvt.u32.u64 %0, t; }"
        : "=r"(a) : "l"(p));
    return a;
}
#define SW128(o) ((o) ^ (((o) >> 3) & 0x70))

#define MBAR_INIT(mb, c)  asm volatile("mbarrier.init.shared.b64 [%0], %1;" :: "r"((uint32_t)(mb)), "r"((uint32_t)(c)) : "memory")
#define MBAR_EXPECT(mb, n) asm volatile("mbarrier.arrive.expect_tx.shared.b64 _, [%0], %1;" :: "r"((uint32_t)(mb)), "r"((uint32_t)(n)) : "memory")
#define MBAR_ARRIVE(mb) asm volatile("mbarrier.arrive.shared.b64 _, [%0];" :: "r"((uint32_t)(mb)) : "memory")
#define MBAR_WAIT(mb, par) do {                                              \
    asm volatile("{\n\t.reg .pred P;\nWL%=:\n\t"                             \
        "mbarrier.try_wait.parity.acquire.cta.shared::cta.b64 P, [%0], %1, 0x989680;\n\t" \
        "@P bra.uni WD%=;\n\tbra.uni WL%=;\nWD%=:\n\t}"                      \
        :: "r"((uint32_t)(mb)), "r"((uint32_t)(par)) : "memory");            \
} while (0)
#define CP_BULK(dst, src, bytes, mbar) \
    asm volatile("cp.async.bulk.shared::cluster.global.mbarrier::complete_tx::bytes [%0], [%1], %2, [%3];" \
        :: "r"((uint32_t)(dst)), "l"(src), "r"((uint32_t)(bytes)), "r"((uint32_t)(mbar)) : "memory")

#define LDSM_X4(r0, r1, r2, r3, addr) \
    asm volatile("ldmatrix.sync.aligned.m8n8.x4.shared.b16 {%0,%1,%2,%3}, [%4];" \
                 : "=r"(r0), "=r"(r1), "=r"(r2), "=r"(r3) : "r"(addr))
#define LDSM_X4_T(r0, r1, r2, r3, addr) \
    asm volatile("ldmatrix.sync.aligned.m8n8.x4.trans.shared.b16 {%0,%1,%2,%3}, [%4];" \
                 : "=r"(r0), "=r"(r1), "=r"(r2), "=r"(r3) : "r"(addr))

#define MMA_BF16(c0, c1, c2, c3, a0, a1, a2, a3, b0, b1) \
    asm volatile("mma.sync.aligned.m16n8k16.row.col.f32.bf16.bf16.f32 " \
                 "{%0,%1,%2,%3}, {%4,%5,%6,%7}, {%8,%9}, {%0,%1,%2,%3};" \
                 : "+f"(c0), "+f"(c1), "+f"(c2), "+f"(c3) \
                 : "r"(a0), "r"(a1), "r"(a2), "r"(a3), "r"(b0), "r"(b1))

#define PACK_BF16X2(d, lof, hif) \
    asm("cvt.rn.bf16x2.f32 %0, %1, %2;" : "=r"(d) : "f"(hif), "f"(lof))

// ---------------------------------------------------------------------------
// Tiled-layout store helpers.
// ---------------------------------------------------------------------------
__device__ __forceinline__ void st_gemm_tile(__nv_bfloat16* Y, int row, int col,
                                             int comp, uint32_t val4) {
    size_t t = ((size_t)(row >> 7) * 32 + comp * 16 + (col >> 6)) * 16384;
    uint32_t bo = SW128((uint32_t)((row & 127) * 128 + (col & 63) * 2));
    *(uint32_t*)((char*)Y + t + bo) = val4;
}
__device__ __forceinline__ void st_flash_tile(__nv_bfloat16* Y, int row, int col,
                                              int comp, uint32_t val4) {
    size_t t = (((size_t)(row >> 6) * 16 + (col >> 6)) * 2 + comp) * 8192;
    uint32_t bo = SW128((uint32_t)((row & 63) * 128 + (col & 63) * 2));
    *(uint32_t*)((char*)Y + t + bo) = val4;
}

// ---------------------------------------------------------------------------
// Multi-tensor fp32 -> (hi, lo) bf16 split (GEMM-tiled out). grid.y = tensor.
// ---------------------------------------------------------------------------
struct SplitArgs {
    const float* X[4];
    __nv_bfloat16* Y[4];
};

__global__ __launch_bounds__(256) void split_bf16_multi(SplitArgs a, int n4)
{
    int i = blockIdx.x * 256 + threadIdx.x;
    if (i >= n4) return;
    const float* X = a.X[blockIdx.y];
    __nv_bfloat16* Y = a.Y[blockIdx.y];
    int r  = i >> 8;
    int c4 = (i & 255) * 4;
    float4 x = *(const float4*)&X[(size_t)r * 1024 + c4];
    float xs[4] = {x.x, x.y, x.z, x.w};
    __nv_bfloat16 hi[4], lo[4];
    #pragma unroll
    for (int j = 0; j < 4; j++) {
        hi[j] = __float2bfloat16(xs[j]);
        lo[j] = __float2bfloat16(xs[j] - __bfloat162float(hi[j]));
    }
    size_t thi = ((size_t)(r >> 7) * 32 + (c4 >> 6)) * 16384;
    size_t tlo = ((size_t)(r >> 7) * 32 + 16 + (c4 >> 6)) * 16384;
    uint32_t bo = SW128((uint32_t)((r & 127) * 128 + (c4 & 63) * 2));
    *(uint2*)((char*)Y + thi + bo) = *(uint2*)hi;
    *(uint2*)((char*)Y + tlo + bo) = *(uint2*)lo;
}

// ---------------------------------------------------------------------------
// GEMM core: one 128x128 tile. A-ring[3] + W-ring[3] of 16KB slots, every
// tile fetched once. product() uses explicit register double-buffering:
// fragments for ks+1 are prefetched before the ks MMAs issue, hiding LDSM
// latency behind tensor work. 2 CTAs/SM.
// ---------------------------------------------------------------------------
constexpr int GEMM_SMEM = 98304 + 128;    // A-ring 48K | W-ring 48K | ctrl

template<bool SPLIT_OUT>
__device__ __forceinline__ void gemm_tile_body(
    const __nv_bfloat16* __restrict__ A, const __nv_bfloat16* __restrict__ W,
    const float* __restrict__ bias, float* __restrict__ C,
    __nv_bfloat16* __restrict__ Y, int N, int bm, int bn)
{
    extern __shared__ char smem[];
    const uint32_t sb = smem_u32(smem);
    const int tid  = threadIdx.x;
    const int lane = tid & 31;
    const int wid  = tid >> 5;
    const int wm   = wid >> 2;
    const int wn   = wid & 3;
    const int m0 = bm * 128;
    const int n0 = bn * 128;
    const uint32_t mbAF = sb + 98304;         // A full[3]
    const uint32_t mbWF = mbAF + 24;          // W full[3]
    const uint32_t mbAE = mbAF + 48;          // A empty[3], count 256
    const uint32_t mbWE = mbAF + 72;          // W empty[3], count 256

    if (tid == 0) {
        #pragma unroll
        for (int s3 = 0; s3 < 3; s3++) {
            MBAR_INIT(mbAF + s3 * 8, 1);
            MBAR_INIT(mbWF + s3 * 8, 1);
            MBAR_INIT(mbAE + s3 * 8, 256);
            MBAR_INIT(mbWE + s3 * 8, 256);
        }
    }
    __syncthreads();

    auto issueA = [&](int n) {
        int slot = n % 3;
        if (n >= 3) MBAR_WAIT(mbAE + slot * 8, ((n - 3) / 3) & 1);
        int t = (n & 1) ? 16 + (n >> 1) : (n >> 1);
        const char* src = (const char*)A + ((size_t)bm * 32 + t) * 16384;
        MBAR_EXPECT(mbAF + slot * 8, 16384);
        CP_BULK(sb + slot * 16384, src, 16384, mbAF + slot * 8);
    };
    auto issueW = [&](int n) {
        int slot = n % 3;
        if (n >= 3) MBAR_WAIT(mbWE + slot * 8, ((n - 3) / 3) & 1);
        int t = (n & 1) ? 16 + (n >> 1) : (n >> 1);
        const char* src = (const char*)W + ((size_t)bn * 32 + t) * 16384;
        MBAR_EXPECT(mbWF + slot * 8, 16384);
        CP_BULK(sb + 49152 + slot * 16384, src, 16384, mbWF + slot * 8);
    };
    if (tid == 0) {
        #pragma unroll
        for (int n = 0; n < 3; n++) { issueA(n); issueW(n); }
    }

    float acc[4][4][4];
    #pragma unroll
    for (int i = 0; i < 4; i++)
        #pragma unroll
        for (int j = 0; j < 4; j++)
            #pragma unroll
            for (int q = 0; q < 4; q++) acc[i][j][q] = 0.f;

    const int a_row = wm * 64 + (lane & 15);
    const int a_kby = (lane >> 4) * 16;
    const int b_row = wn * 32 + (lane & 7) + ((lane >> 3) & 1) * 8;

    const uint32_t lane7x = (uint32_t)((lane & 7) * 16);
    uint32_t xab[4];
    #pragma unroll
    for (int ks = 0; ks < 4; ks++)
        xab[ks] = (uint32_t)((ks * 32 + a_kby)) ^ lane7x;
    const uint32_t rowA = (uint32_t)(a_row * 128);
    const uint32_t rowB = (uint32_t)(b_row * 128);

    // One K=64 product, register-pipelined over the 4 ks steps.
    auto product = [&](int as, int ws) {
        const uint32_t a_base = sb + as * 16384 + rowA;
        const uint32_t w_base = sb + 49152 + ws * 16384 + rowB;
        uint32_t Af[2][4][4], Bf[2][4][2];

        // Prologue: fragments for ks=0 into buffer 0.
        #pragma unroll
        for (int mi = 0; mi < 4; mi++)
            LDSM_X4(Af[0][mi][0], Af[0][mi][1], Af[0][mi][2], Af[0][mi][3],
                    a_base + mi * 2048 + xab[0]);
        {
            uint32_t r0, r1, r2, r3;
            LDSM_X4(r0, r1, r2, r3, w_base + xab[0]);
            Bf[0][0][0] = r0; Bf[0][0][1] = r2; Bf[0][1][0] = r1; Bf[0][1][1] = r3;
            LDSM_X4(r0, r1, r2, r3, w_base + 2048 + xab[0]);
            Bf[0][2][0] = r0; Bf[0][2][1] = r2; Bf[0][3][0] = r1; Bf[0][3][1] = r3;
        }

        #pragma unroll
        for (int ks = 0; ks < 4; ks++) {
            const int cur = ks & 1, nxt = cur ^ 1;
            if (ks < 3) {
                // Prefetch ks+1 fragments; MMAs below don't depend on them,
                // so the tensor pipe keeps issuing while these loads fly.
                #pragma unroll
                for (int mi = 0; mi < 4; mi++)
                    LDSM_X4(Af[nxt][mi][0], Af[nxt][mi][1],
                            Af[nxt][mi][2], Af[nxt][mi][3],
                            a_base + mi * 2048 + xab[ks + 1]);
                uint32_t r0, r1, r2, r3;
                LDSM_X4(r0, r1, r2, r3, w_base + xab[ks + 1]);
                Bf[nxt][0][0] = r0; Bf[nxt][0][1] = r2;
                Bf[nxt][1][0] = r1; Bf[nxt][1][1] = r3;
                LDSM_X4(r0, r1, r2, r3, w_base + 2048 + xab[ks + 1]);
                Bf[nxt][2][0] = r0; Bf[nxt][2][1] = r2;
                Bf[nxt][3][0] = r1; Bf[nxt][3][1] = r3;
            }
            #pragma unroll
            for (int mi = 0; mi < 4; mi++)
                #pragma unroll
                for (int nj = 0; nj < 4; nj++)
                    MMA_BF16(acc[mi][nj][0], acc[mi][nj][1],
                             acc[mi][nj][2], acc[mi][nj][3],
                             Af[cur][mi][0], Af[cur][mi][1],
                             Af[cur][mi][2], Af[cur][mi][3],
                             Bf[cur][nj][0], Bf[cur][nj][1]);
        }
    };

    for (int i = 0; i < 16; i++) {
        const int nhi = 2 * i, nlo = 2 * i + 1;
        const int sh = nhi % 3, sl = nlo % 3;
        const int ph = (nhi / 3) & 1, pl = (nlo / 3) & 1;

        // c0: A_hi * W_hi
        MBAR_WAIT(mbAF + sh * 8, ph);
        MBAR_WAIT(mbWF + sh * 8, ph);
        product(sh, sh);
        // c1: A_lo * W_hi  (then release A_lo, W_hi)
        MBAR_WAIT(mbAF + sl * 8, pl);
        product(sl, sh);
        MBAR_ARRIVE(mbAE + sl * 8);
        MBAR_ARRIVE(mbWE + sh * 8);
        // c2: A_hi * W_lo  (then release A_hi, W_lo)
        MBAR_WAIT(mbWF + sl * 8, pl);
        product(sh, sl);
        MBAR_ARRIVE(mbAE + sh * 8);
        MBAR_ARRIVE(mbWE + sl * 8);

        if (tid == 0) {
            if (nhi + 3 < 32) { issueA(nhi + 3); issueW(nhi + 3); }
            if (nlo + 3 < 32) { issueA(nlo + 3); issueW(nlo + 3); }
        }
    }

    const int erow = m0 + wm * 64 + (lane >> 2);
    const int ecol = n0 + wn * 32 + (lane & 3) * 2;
    #pragma unroll
    for (int nj = 0; nj < 4; nj++) {
        float2 bv = *(const float2*)&bias[ecol + nj * 8];
        #pragma unroll
        for (int mi = 0; mi < 4; mi++) {
            int row0 = erow + mi * 16;
            int cc   = ecol + nj * 8;
            float e0 = acc[mi][nj][0] + bv.x;
            float e1 = acc[mi][nj][1] + bv.y;
            float e2 = acc[mi][nj][2] + bv.x;
            float e3 = acc[mi][nj][3] + bv.y;
            if (SPLIT_OUT) {
                uint32_t hi0, hi1, lo0, lo1;
                PACK_BF16X2(hi0, e0, e1);
                PACK_BF16X2(hi1, e2, e3);
                float h0 = __uint_as_float(hi0 << 16);
                float h1 = __uint_as_float(hi0 & 0xFFFF0000u);
                float h2 = __uint_as_float(hi1 << 16);
                float h3 = __uint_as_float(hi1 & 0xFFFF0000u);
                PACK_BF16X2(lo0, e0 - h0, e1 - h1);
                PACK_BF16X2(lo1, e2 - h2, e3 - h3);
                st_flash_tile(Y, row0,     cc, 0, hi0);
                st_flash_tile(Y, row0,     cc, 1, lo0);
                st_flash_tile(Y, row0 + 8, cc, 0, hi1);
                st_flash_tile(Y, row0 + 8, cc, 1, lo1);
            } else {
                float2 v0 = {e0, e1}, v1 = {e2, e3};
                *(float2*)&C[(size_t)row0 * N + cc] = v0;
                *(float2*)&C[(size_t)(row0 + 8) * N + cc] = v1;
            }
        }
    }
}

// Merged Q/K/V projection: grid (8, 32, 3); z selects tensor.
struct QKVArgs {
    const __nv_bfloat16* A[3];
    const __nv_bfloat16* W[3];
    const float* bias[3];
    __nv_bfloat16* Y[3];
};

__global__ __launch_bounds__(256, 2) void gemm_qkv(QKVArgs a)
{
    int z = blockIdx.z;
    gemm_tile_body<true>(a.A[z], a.W[z], a.bias[z], nullptr, a.Y[z], D_,
                         blockIdx.y, blockIdx.x);
}

__global__ __launch_bounds__(256, 2) void gemm_out(
    const __nv_bfloat16* __restrict__ A, const __nv_bfloat16* __restrict__ W,
    const float* __restrict__ bias, float* __restrict__ C, int N)
{
    gemm_tile_body<false>(A, W, bias, C, nullptr, N, blockIdx.y, blockIdx.x);
}

// ---------------------------------------------------------------------------
// Tensor-core flash attention (causal) — unchanged from R9/R11.
// ---------------------------------------------------------------------------
constexpr int FLASH_CTRL = 98304;
constexpr int FLASH_SMEM = FLASH_CTRL + 64;

__global__ __launch_bounds__(256, 2) void flash_mma(
    const __nv_bfloat16* __restrict__ Qbf, const __nv_bfloat16* __restrict__ Kbf,
    const __nv_bfloat16* __restrict__ Vbf, __nv_bfloat16* __restrict__ Cbf)
{
    extern __shared__ char smem[];
    const uint32_t sb = smem_u32(smem);
    const int bid = blockIdx.x;
    const int qt = (S_ / 128 - 1) - (bid >> 5);
    const int bh = bid & 31;
    const int b  = bh >> 4;
    const int h  = bh & 15;
    const int tid  = threadIdx.x;
    const int lane = tid & 31;
    const int w    = tid >> 5;

    const uint32_t QHI = 0, QLO = 16384;
    auto KHI = [](int bf) { return 32768u + bf * 16384u; };
    auto VHI = [](int bf) { return 65536u + bf * 16384u; };
    const uint32_t mbQ = sb + FLASH_CTRL;
    const uint32_t mbF = mbQ + 8;
    const uint32_t mbE = mbQ + 24;

    if (tid == 0) {
        MBAR_INIT(mbQ, 1);
        MBAR_INIT(mbF, 1);       MBAR_INIT(mbF + 8, 1);
        MBAR_INIT(mbE, 256);     MBAR_INIT(mbE + 8, 256);
    }
    __syncthreads();

    if (tid == 0) {
        MBAR_EXPECT(mbQ, 32768);
        #pragma unroll
        for (int j = 0; j < 2; j++)
            #pragma unroll
            for (int comp = 0; comp < 2; comp++) {
                const char* src = (const char*)Qbf +
                    (((size_t)(b * 32 + 2 * qt + j) * 16 + h) * 2 + comp) * 8192;
                CP_BULK(sb + (comp ? QLO : QHI) + j * 8192, src, 8192, mbQ);
            }
    }

    auto issueKV = [&](int kt, int bf) {
        int r = kt >> 1;
        if (r >= 1) MBAR_WAIT(mbE + bf * 8, (r - 1) & 1);
        uint32_t mbs = mbF + bf * 8;
        MBAR_EXPECT(mbs, 32768);
        size_t rb = (size_t)(b * 32 + kt) * 16 + h;
        #pragma unroll
        for (int comp = 0; comp < 2; comp++) {
            CP_BULK(sb + KHI(bf) + comp * 8192u,
                    (const char*)Kbf + (rb * 2 + comp) * 8192, 8192, mbs);
            CP_BULK(sb + VHI(bf) + comp * 8192u,
                    (const char*)Vbf + (rb * 2 + comp) * 8192, 8192, mbs);
        }
    };

    float ctx[8][4];
    #pragma unroll
    for (int nj = 0; nj < 8; nj++)
        #pragma unroll
        for (int cc = 0; cc < 4; cc++) ctx[nj][cc] = 0.f;
    float m0 = -1e30f, m1 = -1e30f, l0 = 0.f, l1 = 0.f;

    const int nkt = 2 * (qt + 1);
    if (tid == 0) {
        issueKV(0, 0);
        if (nkt > 1) issueKV(1, 1);
    }

    const int a_row = w * 16 + (lane & 15);
    const int a_kby = (lane >> 4) * 16;
    const int b_row = (lane & 7) + ((lane >> 3) & 1) * 8;
    const int vg = lane >> 3, vi = lane & 7;
    const int qrow0 = qt * 128 + w * 16 + (lane >> 2);

    const uint32_t lane7x = (uint32_t)((lane & 7) * 16);
    uint32_t xab[4], xv[4];
    #pragma unroll
    for (int ks = 0; ks < 4; ks++)
        xab[ks] = (uint32_t)(ks * 32 + a_kby) ^ lane7x;
    #pragma unroll
    for (int nb = 0; nb < 4; nb++)
        xv[nb] = (uint32_t)(nb * 32 + (vg >> 1) * 16) ^ lane7x;
    const uint32_t rowQ = (uint32_t)(a_row * 128);
    const uint32_t rowK = (uint32_t)(b_row * 128);
    const uint32_t rowV = (uint32_t)(((vg & 1) * 8 + vi) * 128);

    MBAR_WAIT(mbQ, 0);

    for (int kt = 0; kt < nkt; kt++) {
        const int bf = kt & 1;
        MBAR_WAIT(mbF + bf * 8, (kt >> 1) & 1);
        const bool active = (kt * 64 <= qt * 128 + w * 16 + 15);

        if (active) {
            const uint32_t kh_s = sb + KHI(bf) + rowK;
            const uint32_t vh_s = sb + VHI(bf) + rowV;
            const uint32_t qh_s = sb + QHI + rowQ;
            const uint32_t ql_s = sb + QLO + rowQ;

            float sc[8][4];
            #pragma unroll
            for (int nj = 0; nj < 8; nj++)
                #pragma unroll
                for (int cc = 0; cc < 4; cc++) sc[nj][cc] = 0.f;

            #pragma unroll
            for (int ks = 0; ks < 4; ks++) {
                uint32_t bk[8][2];
                #pragma unroll
                for (int nj2 = 0; nj2 < 4; nj2++) {
                    uint32_t r0, r1, r2, r3;
                    LDSM_X4(r0, r1, r2, r3, kh_s + nj2 * 2048 + xab[ks]);
                    bk[nj2 * 2][0] = r0; bk[nj2 * 2][1] = r2;
                    bk[nj2 * 2 + 1][0] = r1; bk[nj2 * 2 + 1][1] = r3;
                }
                uint32_t a0, a1, a2, a3;
                LDSM_X4(a0, a1, a2, a3, qh_s + xab[ks]);
                #pragma unroll
                for (int nj = 0; nj < 8; nj++)
                    MMA_BF16(sc[nj][0], sc[nj][1], sc[nj][2], sc[nj][3],
                             a0, a1, a2, a3, bk[nj][0], bk[nj][1]);
                LDSM_X4(a0, a1, a2, a3, ql_s + xab[ks]);
                #pragma unroll
                for (int nj = 0; nj < 8; nj++)
                    MMA_BF16(sc[nj][0], sc[nj][1], sc[nj][2], sc[nj][3],
                             a0, a1, a2, a3, bk[nj][0], bk[nj][1]);
            }
            #pragma unroll
            for (int ks = 0; ks < 4; ks++) {
                uint32_t bk[8][2];
                #pragma unroll
                for (int nj2 = 0; nj2 < 4; nj2++) {
                    uint32_t r0, r1, r2, r3;
                    LDSM_X4(r0, r1, r2, r3, kh_s + 8192u + nj2 * 2048 + xab[ks]);
                    bk[nj2 * 2][0] = r0; bk[nj2 * 2][1] = r2;
                    bk[nj2 * 2 + 1][0] = r1; bk[nj2 * 2 + 1][1] = r3;
                }
                uint32_t a0, a1, a2, a3;
                LDSM_X4(a0, a1, a2, a3, qh_s + xab[ks]);
                #pragma unroll
                for (int nj = 0; nj < 8; nj++)
                    MMA_BF16(sc[nj][0], sc[nj][1], sc[nj][2], sc[nj][3],
                             a0, a1, a2, a3, bk[nj][0], bk[nj][1]);
            }

            const bool edge = (kt * 64 + 63 > qt * 128 + w * 16);
            const int kbase = kt * 64 + (lane & 3) * 2;
            #pragma unroll
            for (int nj = 0; nj < 8; nj++)
                #pragma unroll
                for (int cc = 0; cc < 4; cc++) {
                    float sv = sc[nj][cc] * 0.125f;
                    if (edge) {
                        int k = kbase + nj * 8 + (cc & 1);
                        int q = qrow0 + ((cc >> 1) << 3);
                        if (k > q) sv = -1e30f;
                    }
                    sc[nj][cc] = sv;
                }

            float mx0 = -1e30f, mx1 = -1e30f;
            #pragma unroll
            for (int nj = 0; nj < 8; nj++) {
                mx0 = fmaxf(mx0, fmaxf(sc[nj][0], sc[nj][1]));
                mx1 = fmaxf(mx1, fmaxf(sc[nj][2], sc[nj][3]));
            }
            mx0 = fmaxf(mx0, __shfl_xor_sync(0xffffffffu, mx0, 1));
            mx0 = fmaxf(mx0, __shfl_xor_sync(0xffffffffu, mx0, 2));
            mx1 = fmaxf(mx1, __shfl_xor_sync(0xffffffffu, mx1, 1));
            mx1 = fmaxf(mx1, __shfl_xor_sync(0xffffffffu, mx1, 2));
            float mn0 = fmaxf(m0, mx0), mn1 = fmaxf(m1, mx1);
            float al0 = __expf(m0 - mn0), al1 = __expf(m1 - mn1);
            m0 = mn0; m1 = mn1;
            float sum0 = 0.f, sum1 = 0.f;
            #pragma unroll
            for (int nj = 0; nj < 8; nj++) {
                sc[nj][0] = __expf(sc[nj][0] - mn0); sum0 += sc[nj][0];
                sc[nj][1] = __expf(sc[nj][1] - mn0); sum0 += sc[nj][1];
                sc[nj][2] = __expf(sc[nj][2] - mn1); sum1 += sc[nj][2];
                sc[nj][3] = __expf(sc[nj][3] - mn1); sum1 += sc[nj][3];
            }
            l0 = l0 * al0 + sum0;
            l1 = l1 * al1 + sum1;
            #pragma unroll
            for (int nj = 0; nj < 8; nj++) {
                ctx[nj][0] *= al0; ctx[nj][1] *= al0;
                ctx[nj][2] *= al1; ctx[nj][3] *= al1;
            }

            #pragma unroll
            for (int ks = 0; ks < 4; ks++) {
                float* p0 = sc[2 * ks];
                float* p1 = sc[2 * ks + 1];
                uint32_t ph0, ph1, ph2, ph3, pl0, pl1, pl2, pl3;
                PACK_BF16X2(ph0, p0[0], p0[1]);
                PACK_BF16X2(ph1, p0[2], p0[3]);
                PACK_BF16X2(ph2, p1[0], p1[1]);
                PACK_BF16X2(ph3, p1[2], p1[3]);
                {
                    float r00 = p0[0] - __uint_as_float(ph0 << 16);
                    float r01 = p0[1] - __uint_as_float(ph0 & 0xFFFF0000u);
                    float r02 = p0[2] - __uint_as_float(ph1 << 16);
                    float r03 = p0[3] - __uint_as_float(ph1 & 0xFFFF0000u);
                    float r10 = p1[0] - __uint_as_float(ph2 << 16);
                    float r11 = p1[1] - __uint_as_float(ph2 & 0xFFFF0000u);
                    float r12 = p1[2] - __uint_as_float(ph3 << 16);
                    float r13 = p1[3] - __uint_as_float(ph3 & 0xFFFF0000u);
                    PACK_BF16X2(pl0, r00, r01);
                    PACK_BF16X2(pl1, r02, r03);
                    PACK_BF16X2(pl2, r10, r11);
                    PACK_BF16X2(pl3, r12, r13);
                }
                #pragma unroll
                for (int nb = 0; nb < 4; nb++) {
                    uint32_t r0, r1, r2, r3;
                    LDSM_X4_T(r0, r1, r2, r3, vh_s + ks * 2048 + xv[nb]);
                    MMA_BF16(ctx[2*nb][0], ctx[2*nb][1], ctx[2*nb][2], ctx[2*nb][3],
                             ph0, ph1, ph2, ph3, r0, r1);
                    MMA_BF16(ctx[2*nb+1][0], ctx[2*nb+1][1], ctx[2*nb+1][2], ctx[2*nb+1][3],
                             ph0, ph1, ph2, ph3, r2, r3);
                    MMA_BF16(ctx[2*nb][0], ctx[2*nb][1], ctx[2*nb][2], ctx[2*nb][3],
                             pl0, pl1, pl2, pl3, r0, r1);
                    MMA_BF16(ctx[2*nb+1][0], ctx[2*nb+1][1], ctx[2*nb+1][2], ctx[2*nb+1][3],
                             pl0, pl1, pl2, pl3, r2, r3);
                }
                #pragma unroll
                for (int nb = 0; nb < 4; nb++) {
                    uint32_t r0, r1, r2, r3;
                    LDSM_X4_T(r0, r1, r2, r3, vh_s + 8192u + ks * 2048 + xv[nb]);
                    MMA_BF16(ctx[2*nb][0], ctx[2*nb][1], ctx[2*nb][2], ctx[2*nb][3],
                             ph0, ph1, ph2, ph3, r0, r1);
                    MMA_BF16(ctx[2*nb+1][0], ctx[2*nb+1][1], ctx[2*nb+1][2], ctx[2*nb+1][3],
                             ph0, ph1, ph2, ph3, r2, r3);
                }
            }
        }

        MBAR_ARRIVE(mbE + bf * 8);
        if (tid == 0 && kt + 2 < nkt) issueKV(kt + 2, bf);
    }

    l0 += __shfl_xor_sync(0xffffffffu, l0, 1);
    l0 += __shfl_xor_sync(0xffffffffu, l0, 2);
    l1 += __shfl_xor_sync(0xffffffffu, l1, 1);
    l1 += __shfl_xor_sync(0xffffffffu, l1, 2);
    const float inv0 = 1.f / l0, inv1 = 1.f / l1;

    const int grow = b * 2048 + qt * 128 + w * 16 + (lane >> 2);
    const int colb = h * 64 + (lane & 3) * 2;
    #pragma unroll
    for (int nj = 0; nj < 8; nj++) {
        int cc = colb + nj * 8;
        float e0 = ctx[nj][0] * inv0, e1 = ctx[nj][1] * inv0;
        float e2 = ctx[nj][2] * inv1, e3 = ctx[nj][3] * inv1;
        uint32_t hi0, hi1, lo0, lo1;
        PACK_BF16X2(hi0, e0, e1);
        PACK_BF16X2(hi1, e2, e3);
        float h0 = __uint_as_float(hi0 << 16);
        float h1 = __uint_as_float(hi0 & 0xFFFF0000u);
        float h2 = __uint_as_float(hi1 << 16);
        float h3 = __uint_as_float(hi1 & 0xFFFF0000u);
        PACK_BF16X2(lo0, e0 - h0, e1 - h1);
        PACK_BF16X2(lo1, e2 - h2, e3 - h3);
        st_gemm_tile(Cbf, grow,     cc, 0, hi0);
        st_gemm_tile(Cbf, grow,     cc, 1, lo0);
        st_gemm_tile(Cbf, grow + 8, cc, 0, hi1);
        st_gemm_tile(Cbf, grow + 8, cc, 1, lo1);
    }
}

// ---------------------------------------------------------------------------
// Launch
// ---------------------------------------------------------------------------
extern "C" void kernel_launch(void* const* d_in, const int* in_sizes, int n_in,
                              void* d_out, int out_size)
{
    const float* query = (const float*)d_in[0];
    const float* key   = (const float*)d_in[1];
    const float* value = (const float*)d_in[2];
    // d_in[3] = mask — analytically causal (triu k=1).
    const float* Wq = (const float*)d_in[4];
    const float* bq = (const float*)d_in[5];
    const float* Wk = (const float*)d_in[6];
    const float* bk = (const float*)d_in[7];
    const float* Wv = (const float*)d_in[8];
    const float* bv = (const float*)d_in[9];
    const float* Wo = (const float*)d_in[10];
    const float* bo = (const float*)d_in[11];
    float* out = (float*)d_out;

    float* f32 = nullptr;
    __nv_bfloat16* act = nullptr;
    __nv_bfloat16* wbf = nullptr;
    cudaGetSymbolAddress((void**)&f32, g_f32);
    cudaGetSymbolAddress((void**)&act, g_act_bf);
    cudaGetSymbolAddress((void**)&wbf, g_w_bf);

    const size_t TSZ = (size_t)M_ * KP_;
    __nv_bfloat16* pool = (__nv_bfloat16*)f32;
    __nv_bfloat16* Qbf = pool;            // flash-tiled
    __nv_bfloat16* Kbf = pool + TSZ;      // flash-tiled
    __nv_bfloat16* Vbf = pool + 2 * TSZ;  // flash-tiled
    __nv_bfloat16* Cbf = pool + 3 * TSZ;  // gemm-tiled

    __nv_bfloat16* qc = act;              // gemm-tiled
    __nv_bfloat16* kc = act + TSZ;
    __nv_bfloat16* vc = act + 2 * TSZ;
    __nv_bfloat16* wqc = wbf;             // gemm-tiled
    __nv_bfloat16* wkc = wbf + (size_t)D_ * KP_;
    __nv_bfloat16* wvc = wbf + 2 * (size_t)D_ * KP_;
    __nv_bfloat16* woc = wbf + 3 * (size_t)D_ * KP_;

    cudaFuncSetAttribute(gemm_qkv,
                         cudaFuncAttributeMaxDynamicSharedMemorySize, GEMM_SMEM);
    cudaFuncSetAttribute(gemm_out,
                         cudaFuncAttributeMaxDynamicSharedMemorySize, GEMM_SMEM);
    cudaFuncSetAttribute(flash_mma,
                         cudaFuncAttributeMaxDynamicSharedMemorySize, FLASH_SMEM);

    const int n4_w = D_ * 256;
    const int n4_a = M_ * 256;
    {
        SplitArgs wa;
        wa.X[0] = Wq; wa.X[1] = Wk; wa.X[2] = Wv; wa.X[3] = Wo;
        wa.Y[0] = wqc; wa.Y[1] = wkc; wa.Y[2] = wvc; wa.Y[3] = woc;
        split_bf16_multi<<<dim3((n4_w + 255) / 256, 4), 256>>>(wa, n4_w);
        SplitArgs aa;
        aa.X[0] = query; aa.X[1] = key; aa.X[2] = value; aa.X[3] = query;
        aa.Y[0] = qc; aa.Y[1] = kc; aa.Y[2] = vc; aa.Y[3] = qc;
        split_bf16_multi<<<dim3((n4_a + 255) / 256, 3), 256>>>(aa, n4_a);
    }

    {
        QKVArgs qa;
        qa.A[0] = qc;  qa.A[1] = kc;  qa.A[2] = vc;
        qa.W[0] = wqc; qa.W[1] = wkc; qa.W[2] = wvc;
        qa.bias[0] = bq; qa.bias[1] = bk; qa.bias[2] = bv;
        qa.Y[0] = Qbf; qa.Y[1] = Kbf; qa.Y[2] = Vbf;
        gemm_qkv<<<dim3(D_ / 128, M_ / 128, 3), 256, GEMM_SMEM>>>(qa);
    }

    flash_mma<<<(S_ / 128) * B_ * H_, 256, FLASH_SMEM>>>(Qbf, Kbf, Vbf, Cbf);

    gemm_out<<<dim3(D_ / 128, M_ / 128), 256, GEMM_SMEM>>>(Cbf, woc, bo, out, D_);
}

// round 13
// speedup vs baseline: 1.0372x; 1.0372x over previous
#include <cuda_runtime.h>
#include <cuda_bf16.h>
#include <cstdint>
#include <cstddef>

// Problem constants
constexpr int B_  = 2;
constexpr int S_  = 2048;
constexpr int D_  = 1024;
constexpr int H_  = 16;
constexpr int HD_ = 64;
constexpr int M_   = B_ * S_;                     // 4096
constexpr int KP_  = 2 * D_;                      // 2048 (hi|lo side by side)

// ---------------------------------------------------------------------------
// Scratch (__device__ globals; no allocation allowed)
// ---------------------------------------------------------------------------
__device__ float g_f32[4 * B_ * S_ * D_];                    // pool: Qbf,Kbf,Vbf,Cbf
__device__ __nv_bfloat16 g_act_bf[4 * (size_t)M_ * KP_];     // qc, kc, vc (gemm-tiled)
__device__ __nv_bfloat16 g_w_bf[4 * (size_t)D_ * KP_];       // weights (gemm-tiled)

// Work-queue state (reset每 launch by reset_kernel)
__device__ int g_ctr;
__device__ int g_flag[3 * 32 * 8];   // QKV tile done flags (z, bm, bn)
__device__ int g_cdone[32];          // flash row-block completion counts (bm)

// ---------------------------------------------------------------------------
// Helpers (baseline PTX only — sm_90-level, no a-gated instructions)
// ---------------------------------------------------------------------------
__device__ __forceinline__ uint32_t smem_u32(const void* p) {
    uint32_t a;
    asm("{ .reg .u64 t; cvta.to.shared.u64 t, %1; cvt.u32.u64 %0, t; }"
        : "=r"(a) : "l"(p));
    return a;
}
#define SW128(o) ((o) ^ (((o) >> 3) & 0x70))

#define MBAR_INIT(mb, c)  asm volatile("mbarrier.init.shared.b64 [%0], %1;" :: "r"((uint32_t)(mb)), "r"((uint32_t)(c)) : "memory")
#define MBAR_EXPECT(mb, n) asm volatile("mbarrier.arrive.expect_tx.shared.b64 _, [%0], %1;" :: "r"((uint32_t)(mb)), "r"((uint32_t)(n)) : "memory")
#define MBAR_ARRIVE(mb) asm volatile("mbarrier.arrive.shared.b64 _, [%0];" :: "r"((uint32_t)(mb)) : "memory")
#define MBAR_WAIT(mb, par) do {                                              \
    asm volatile("{\n\t.reg .pred P;\nWL%=:\n\t"                             \
        "mbarrier.try_wait.parity.acquire.cta.shared::cta.b64 P, [%0], %1, 0x989680;\n\t" \
        "@P bra.uni WD%=;\n\tbra.uni WL%=;\nWD%=:\n\t}"                      \
        :: "r"((uint32_t)(mb)), "r"((uint32_t)(par)) : "memory");            \
} while (0)
#define CP_BULK(dst, src, bytes, mbar) \
    asm volatile("cp.async.bulk.shared::cluster.global.mbarrier::complete_tx::bytes [%0], [%1], %2, [%3];" \
        :: "r"((uint32_t)(dst)), "l"(src), "r"((uint32_t)(bytes)), "r"((uint32_t)(mbar)) : "memory")

#define LDSM_X4(r0, r1, r2, r3, addr) \
    asm volatile("ldmatrix.sync.aligned.m8n8.x4.shared.b16 {%0,%1,%2,%3}, [%4];" \
                 : "=r"(r0), "=r"(r1), "=r"(r2), "=r"(r3) : "r"(addr))
#define LDSM_X4_T(r0, r1, r2, r3, addr) \
    asm volatile("ldmatrix.sync.aligned.m8n8.x4.trans.shared.b16 {%0,%1,%2,%3}, [%4];" \
                 : "=r"(r0), "=r"(r1), "=r"(r2), "=r"(r3) : "r"(addr))

#define MMA_BF16(c0, c1, c2, c3, a0, a1, a2, a3, b0, b1) \
    asm volatile("mma.sync.aligned.m16n8k16.row.col.f32.bf16.bf16.f32 " \
                 "{%0,%1,%2,%3}, {%4,%5,%6,%7}, {%8,%9}, {%0,%1,%2,%3};" \
                 : "+f"(c0), "+f"(c1), "+f"(c2), "+f"(c3) \
                 : "r"(a0), "r"(a1), "r"(a2), "r"(a3), "r"(b0), "r"(b1))

#define PACK_BF16X2(d, lof, hif) \
    asm("cvt.rn.bf16x2.f32 %0, %1, %2;" : "=r"(d) : "f"(hif), "f"(lof))

__device__ __forceinline__ void wait_flag(int* f) {
    while (atomicAdd(f, 0) == 0) __nanosleep(64);
}

// ---------------------------------------------------------------------------
// Tiled-layout store helpers.
// ---------------------------------------------------------------------------
__device__ __forceinline__ void st_gemm_tile(__nv_bfloat16* Y, int row, int col,
                                             int comp, uint32_t val4) {
    size_t t = ((size_t)(row >> 7) * 32 + comp * 16 + (col >> 6)) * 16384;
    uint32_t bo = SW128((uint32_t)((row & 127) * 128 + (col & 63) * 2));
    *(uint32_t*)((char*)Y + t + bo) = val4;
}
__device__ __forceinline__ void st_flash_tile(__nv_bfloat16* Y, int row, int col,
                                              int comp, uint32_t val4) {
    size_t t = (((size_t)(row >> 6) * 16 + (col >> 6)) * 2 + comp) * 8192;
    uint32_t bo = SW128((uint32_t)((row & 63) * 128 + (col & 63) * 2));
    *(uint32_t*)((char*)Y + t + bo) = val4;
}

// ---------------------------------------------------------------------------
// Reset queue state (must run first every launch).
// ---------------------------------------------------------------------------
__global__ void reset_kernel()
{
    int i = threadIdx.x;
    if (i == 0) g_ctr = 0;
    for (int j = i; j < 3 * 32 * 8; j += 256) g_flag[j] = 0;
    if (i < 32) g_cdone[i] = 0;
}

// ---------------------------------------------------------------------------
// Multi-tensor fp32 -> (hi, lo) bf16 split (GEMM-tiled out). grid.y = tensor.
// ---------------------------------------------------------------------------
struct SplitArgs {
    const float* X[4];
    __nv_bfloat16* Y[4];
};

__global__ __launch_bounds__(256) void split_bf16_multi(SplitArgs a, int n4)
{
    int i = blockIdx.x * 256 + threadIdx.x;
    if (i >= n4) return;
    const float* X = a.X[blockIdx.y];
    __nv_bfloat16* Y = a.Y[blockIdx.y];
    int r  = i >> 8;
    int c4 = (i & 255) * 4;
    float4 x = *(const float4*)&X[(size_t)r * 1024 + c4];
    float xs[4] = {x.x, x.y, x.z, x.w};
    __nv_bfloat16 hi[4], lo[4];
    #pragma unroll
    for (int j = 0; j < 4; j++) {
        hi[j] = __float2bfloat16(xs[j]);
        lo[j] = __float2bfloat16(xs[j] - __bfloat162float(hi[j]));
    }
    size_t thi = ((size_t)(r >> 7) * 32 + (c4 >> 6)) * 16384;
    size_t tlo = ((size_t)(r >> 7) * 32 + 16 + (c4 >> 6)) * 16384;
    uint32_t bo = SW128((uint32_t)((r & 127) * 128 + (c4 & 63) * 2));
    *(uint2*)((char*)Y + thi + bo) = *(uint2*)hi;
    *(uint2*)((char*)Y + tlo + bo) = *(uint2*)lo;
}

// ---------------------------------------------------------------------------
// GEMM tile body (R11 version): A-ring[3] + W-ring[3], tiles fetched once.
// ---------------------------------------------------------------------------
constexpr int SMEM_CTRL  = 98304;
constexpr int SMEM_TOTAL = SMEM_CTRL + 128;

template<bool SPLIT_OUT>
__device__ void gemm_tile_body(
    const __nv_bfloat16* __restrict__ A, const __nv_bfloat16* __restrict__ W,
    const float* __restrict__ bias, float* __restrict__ C,
    __nv_bfloat16* __restrict__ Y, int N, int bm, int bn)
{
    extern __shared__ char smem[];
    const uint32_t sb = smem_u32(smem);
    const int tid  = threadIdx.x;
    const int lane = tid & 31;
    const int wid  = tid >> 5;
    const int wm   = wid >> 2;
    const int wn   = wid & 3;
    const int m0 = bm * 128;
    const int n0 = bn * 128;
    const uint32_t mbAF = sb + SMEM_CTRL;     // A full[3]
    const uint32_t mbWF = mbAF + 24;          // W full[3]
    const uint32_t mbAE = mbAF + 48;          // A empty[3], count 256
    const uint32_t mbWE = mbAF + 72;          // W empty[3], count 256

    if (tid == 0) {
        #pragma unroll
        for (int s3 = 0; s3 < 3; s3++) {
            MBAR_INIT(mbAF + s3 * 8, 1);
            MBAR_INIT(mbWF + s3 * 8, 1);
            MBAR_INIT(mbAE + s3 * 8, 256);
            MBAR_INIT(mbWE + s3 * 8, 256);
        }
    }
    __syncthreads();

    auto issueA = [&](int n) {
        int slot = n % 3;
        if (n >= 3) MBAR_WAIT(mbAE + slot * 8, ((n - 3) / 3) & 1);
        int t = (n & 1) ? 16 + (n >> 1) : (n >> 1);
        const char* src = (const char*)A + ((size_t)bm * 32 + t) * 16384;
        MBAR_EXPECT(mbAF + slot * 8, 16384);
        CP_BULK(sb + slot * 16384, src, 16384, mbAF + slot * 8);
    };
    auto issueW = [&](int n) {
        int slot = n % 3;
        if (n >= 3) MBAR_WAIT(mbWE + slot * 8, ((n - 3) / 3) & 1);
        int t = (n & 1) ? 16 + (n >> 1) : (n >> 1);
        const char* src = (const char*)W + ((size_t)bn * 32 + t) * 16384;
        MBAR_EXPECT(mbWF + slot * 8, 16384);
        CP_BULK(sb + 49152 + slot * 16384, src, 16384, mbWF + slot * 8);
    };
    if (tid == 0) {
        #pragma unroll
        for (int n = 0; n < 3; n++) { issueA(n); issueW(n); }
    }

    float acc[4][4][4];
    #pragma unroll
    for (int i = 0; i < 4; i++)
        #pragma unroll
        for (int j = 0; j < 4; j++)
            #pragma unroll
            for (int q = 0; q < 4; q++) acc[i][j][q] = 0.f;

    const int a_row = wm * 64 + (lane & 15);
    const int a_kby = (lane >> 4) * 16;
    const int b_row = wn * 32 + (lane & 7) + ((lane >> 3) & 1) * 8;

    const uint32_t lane7x = (uint32_t)((lane & 7) * 16);
    uint32_t xab[4];
    #pragma unroll
    for (int ks = 0; ks < 4; ks++)
        xab[ks] = (uint32_t)((ks * 32 + a_kby)) ^ lane7x;
    const uint32_t rowA = (uint32_t)(a_row * 128);
    const uint32_t rowB = (uint32_t)(b_row * 128);

    auto product = [&](int as, int ws) {
        const uint32_t a_base = sb + as * 16384 + rowA;
        const uint32_t w_base = sb + 49152 + ws * 16384 + rowB;
        #pragma unroll
        for (int ks = 0; ks < 4; ks++) {
            uint32_t Af[4][4], Bf[4][2];
            #pragma unroll
            for (int mi = 0; mi < 4; mi++)
                LDSM_X4(Af[mi][0], Af[mi][1], Af[mi][2], Af[mi][3],
                        a_base + mi * 2048 + xab[ks]);
            {
                uint32_t r0, r1, r2, r3;
                LDSM_X4(r0, r1, r2, r3, w_base + xab[ks]);
                Bf[0][0] = r0; Bf[0][1] = r2; Bf[1][0] = r1; Bf[1][1] = r3;
                LDSM_X4(r0, r1, r2, r3, w_base + 2048 + xab[ks]);
                Bf[2][0] = r0; Bf[2][1] = r2; Bf[3][0] = r1; Bf[3][1] = r3;
            }
            #pragma unroll
            for (int mi = 0; mi < 4; mi++)
                #pragma unroll
                for (int nj = 0; nj < 4; nj++)
                    MMA_BF16(acc[mi][nj][0], acc[mi][nj][1],
                             acc[mi][nj][2], acc[mi][nj][3],
                             Af[mi][0], Af[mi][1], Af[mi][2], Af[mi][3],
                             Bf[nj][0], Bf[nj][1]);
        }
    };

    for (int i = 0; i < 16; i++) {
        const int nhi = 2 * i, nlo = 2 * i + 1;
        const int sh = nhi % 3, sl = nlo % 3;
        const int ph = (nhi / 3) & 1, pl = (nlo / 3) & 1;

        MBAR_WAIT(mbAF + sh * 8, ph);
        MBAR_WAIT(mbWF + sh * 8, ph);
        product(sh, sh);
        MBAR_WAIT(mbAF + sl * 8, pl);
        product(sl, sh);
        MBAR_ARRIVE(mbAE + sl * 8);
        MBAR_ARRIVE(mbWE + sh * 8);
        MBAR_WAIT(mbWF + sl * 8, pl);
        product(sh, sl);
        MBAR_ARRIVE(mbAE + sh * 8);
        MBAR_ARRIVE(mbWE + sl * 8);

        if (tid == 0) {
            if (nhi + 3 < 32) { issueA(nhi + 3); issueW(nhi + 3); }
            if (nlo + 3 < 32) { issueA(nlo + 3); issueW(nlo + 3); }
        }
    }

    const int erow = m0 + wm * 64 + (lane >> 2);
    const int ecol = n0 + wn * 32 + (lane & 3) * 2;
    #pragma unroll
    for (int nj = 0; nj < 4; nj++) {
        float2 bv = *(const float2*)&bias[ecol + nj * 8];
        #pragma unroll
        for (int mi = 0; mi < 4; mi++) {
            int row0 = erow + mi * 16;
            int cc   = ecol + nj * 8;
            float e0 = acc[mi][nj][0] + bv.x;
            float e1 = acc[mi][nj][1] + bv.y;
            float e2 = acc[mi][nj][2] + bv.x;
            float e3 = acc[mi][nj][3] + bv.y;
            if (SPLIT_OUT) {
                uint32_t hi0, hi1, lo0, lo1;
                PACK_BF16X2(hi0, e0, e1);
                PACK_BF16X2(hi1, e2, e3);
                float h0 = __uint_as_float(hi0 << 16);
                float h1 = __uint_as_float(hi0 & 0xFFFF0000u);
                float h2 = __uint_as_float(hi1 << 16);
                float h3 = __uint_as_float(hi1 & 0xFFFF0000u);
                PACK_BF16X2(lo0, e0 - h0, e1 - h1);
                PACK_BF16X2(lo1, e2 - h2, e3 - h3);
                st_flash_tile(Y, row0,     cc, 0, hi0);
                st_flash_tile(Y, row0,     cc, 1, lo0);
                st_flash_tile(Y, row0 + 8, cc, 0, hi1);
                st_flash_tile(Y, row0 + 8, cc, 1, lo1);
            } else {
                float2 v0 = {e0, e1}, v1 = {e2, e3};
                *(float2*)&C[(size_t)row0 * N + cc] = v0;
                *(float2*)&C[(size_t)(row0 + 8) * N + cc] = v1;
            }
        }
    }
}

// ---------------------------------------------------------------------------
// Flash tile body (one (qt, b, h) tile), with QKV readiness flag waits.
// ---------------------------------------------------------------------------
__device__ void flash_tile_body(
    int qt, int b, int h,
    const __nv_bfloat16* __restrict__ Qbf, const __nv_bfloat16* __restrict__ Kbf,
    const __nv_bfloat16* __restrict__ Vbf, __nv_bfloat16* __restrict__ Cbf)
{
    extern __shared__ char smem[];
    const uint32_t sb = smem_u32(smem);
    const int tid  = threadIdx.x;
    const int lane = tid & 31;
    const int w    = tid >> 5;

    const uint32_t QHI = 0, QLO = 16384;
    auto KHI = [](int bf) { return 32768u + bf * 16384u; };
    auto VHI = [](int bf) { return 65536u + bf * 16384u; };
    const uint32_t mbQ = sb + SMEM_CTRL;
    const uint32_t mbF = mbQ + 8;
    const uint32_t mbE = mbQ + 24;

    if (tid == 0) {
        MBAR_INIT(mbQ, 1);
        MBAR_INIT(mbF, 1);       MBAR_INIT(mbF + 8, 1);
        MBAR_INIT(mbE, 256);     MBAR_INIT(mbE + 8, 256);
    }
    __syncthreads();

    if (tid == 0) {
        wait_flag(&g_flag[(0 * 32 + b * 16 + qt) * 8 + (h >> 1)]);
        __threadfence();
        MBAR_EXPECT(mbQ, 32768);
        #pragma unroll
        for (int j = 0; j < 2; j++)
            #pragma unroll
            for (int comp = 0; comp < 2; comp++) {
                const char* src = (const char*)Qbf +
                    (((size_t)(b * 32 + 2 * qt + j) * 16 + h) * 2 + comp) * 8192;
                CP_BULK(sb + (comp ? QLO : QHI) + j * 8192, src, 8192, mbQ);
            }
    }

    auto issueKV = [&](int kt, int bf) {
        int r = kt >> 1;
        if (r >= 1) MBAR_WAIT(mbE + bf * 8, (r - 1) & 1);
        int bmk = b * 16 + (kt >> 1);
        wait_flag(&g_flag[(1 * 32 + bmk) * 8 + (h >> 1)]);
        wait_flag(&g_flag[(2 * 32 + bmk) * 8 + (h >> 1)]);
        __threadfence();
        uint32_t mbs = mbF + bf * 8;
        MBAR_EXPECT(mbs, 32768);
        size_t rb = (size_t)(b * 32 + kt) * 16 + h;
        #pragma unroll
        for (int comp = 0; comp < 2; comp++) {
            CP_BULK(sb + KHI(bf) + comp * 8192u,
                    (const char*)Kbf + (rb * 2 + comp) * 8192, 8192, mbs);
            CP_BULK(sb + VHI(bf) + comp * 8192u,
                    (const char*)Vbf + (rb * 2 + comp) * 8192, 8192, mbs);
        }
    };

    float ctx[8][4];
    #pragma unroll
    for (int nj = 0; nj < 8; nj++)
        #pragma unroll
        for (int cc = 0; cc < 4; cc++) ctx[nj][cc] = 0.f;
    float m0 = -1e30f, m1 = -1e30f, l0 = 0.f, l1 = 0.f;

    const int nkt = 2 * (qt + 1);
    if (tid == 0) {
        issueKV(0, 0);
        if (nkt > 1) issueKV(1, 1);
    }

    const int a_row = w * 16 + (lane & 15);
    const int a_kby = (lane >> 4) * 16;
    const int b_row = (lane & 7) + ((lane >> 3) & 1) * 8;
    const int vg = lane >> 3, vi = lane & 7;
    const int qrow0 = qt * 128 + w * 16 + (lane >> 2);

    const uint32_t lane7x = (uint32_t)((lane & 7) * 16);
    uint32_t xab[4], xv[4];
    #pragma unroll
    for (int ks = 0; ks < 4; ks++)
        xab[ks] = (uint32_t)(ks * 32 + a_kby) ^ lane7x;
    #pragma unroll
    for (int nb = 0; nb < 4; nb++)
        xv[nb] = (uint32_t)(nb * 32 + (vg >> 1) * 16) ^ lane7x;
    const uint32_t rowQ = (uint32_t)(a_row * 128);
    const uint32_t rowK = (uint32_t)(b_row * 128);
    const uint32_t rowV = (uint32_t)(((vg & 1) * 8 + vi) * 128);

    MBAR_WAIT(mbQ, 0);

    for (int kt = 0; kt < nkt; kt++) {
        const int bf = kt & 1;
        MBAR_WAIT(mbF + bf * 8, (kt >> 1) & 1);
        const bool active = (kt * 64 <= qt * 128 + w * 16 + 15);

        if (active) {
            const uint32_t kh_s = sb + KHI(bf) + rowK;
            const uint32_t vh_s = sb + VHI(bf) + rowV;
            const uint32_t qh_s = sb + QHI + rowQ;
            const uint32_t ql_s = sb + QLO + rowQ;

            float sc[8][4];
            #pragma unroll
            for (int nj = 0; nj < 8; nj++)
                #pragma unroll
                for (int cc = 0; cc < 4; cc++) sc[nj][cc] = 0.f;

            #pragma unroll
            for (int ks = 0; ks < 4; ks++) {
                uint32_t bk[8][2];
                #pragma unroll
                for (int nj2 = 0; nj2 < 4; nj2++) {
                    uint32_t r0, r1, r2, r3;
                    LDSM_X4(r0, r1, r2, r3, kh_s + nj2 * 2048 + xab[ks]);
                    bk[nj2 * 2][0] = r0; bk[nj2 * 2][1] = r2;
                    bk[nj2 * 2 + 1][0] = r1; bk[nj2 * 2 + 1][1] = r3;
                }
                uint32_t a0, a1, a2, a3;
                LDSM_X4(a0, a1, a2, a3, qh_s + xab[ks]);
                #pragma unroll
                for (int nj = 0; nj < 8; nj++)
                    MMA_BF16(sc[nj][0], sc[nj][1], sc[nj][2], sc[nj][3],
                             a0, a1, a2, a3, bk[nj][0], bk[nj][1]);
                LDSM_X4(a0, a1, a2, a3, ql_s + xab[ks]);
                #pragma unroll
                for (int nj = 0; nj < 8; nj++)
                    MMA_BF16(sc[nj][0], sc[nj][1], sc[nj][2], sc[nj][3],
                             a0, a1, a2, a3, bk[nj][0], bk[nj][1]);
            }
            #pragma unroll
            for (int ks = 0; ks < 4; ks++) {
                uint32_t bk[8][2];
                #pragma unroll
                for (int nj2 = 0; nj2 < 4; nj2++) {
                    uint32_t r0, r1, r2, r3;
                    LDSM_X4(r0, r1, r2, r3, kh_s + 8192u + nj2 * 2048 + xab[ks]);
                    bk[nj2 * 2][0] = r0; bk[nj2 * 2][1] = r2;
                    bk[nj2 * 2 + 1][0] = r1; bk[nj2 * 2 + 1][1] = r3;
                }
                uint32_t a0, a1, a2, a3;
                LDSM_X4(a0, a1, a2, a3, qh_s + xab[ks]);
                #pragma unroll
                for (int nj = 0; nj < 8; nj++)
                    MMA_BF16(sc[nj][0], sc[nj][1], sc[nj][2], sc[nj][3],
                             a0, a1, a2, a3, bk[nj][0], bk[nj][1]);
            }

            const bool edge = (kt * 64 + 63 > qt * 128 + w * 16);
            const int kbase = kt * 64 + (lane & 3) * 2;
            #pragma unroll
            for (int nj = 0; nj < 8; nj++)
                #pragma unroll
                for (int cc = 0; cc < 4; cc++) {
                    float sv = sc[nj][cc] * 0.125f;
                    if (edge) {
                        int k = kbase + nj * 8 + (cc & 1);
                        int q = qrow0 + ((cc >> 1) << 3);
                        if (k > q) sv = -1e30f;
                    }
                    sc[nj][cc] = sv;
                }

            float mx0 = -1e30f, mx1 = -1e30f;
            #pragma unroll
            for (int nj = 0; nj < 8; nj++) {
                mx0 = fmaxf(mx0, fmaxf(sc[nj][0], sc[nj][1]));
                mx1 = fmaxf(mx1, fmaxf(sc[nj][2], sc[nj][3]));
            }
            mx0 = fmaxf(mx0, __shfl_xor_sync(0xffffffffu, mx0, 1));
            mx0 = fmaxf(mx0, __shfl_xor_sync(0xffffffffu, mx0, 2));
            mx1 = fmaxf(mx1, __shfl_xor_sync(0xffffffffu, mx1, 1));
            mx1 = fmaxf(mx1, __shfl_xor_sync(0xffffffffu, mx1, 2));
            float mn0 = fmaxf(m0, mx0), mn1 = fmaxf(m1, mx1);
            float al0 = __expf(m0 - mn0), al1 = __expf(m1 - mn1);
            m0 = mn0; m1 = mn1;
            float sum0 = 0.f, sum1 = 0.f;
            #pragma unroll
            for (int nj = 0; nj < 8; nj++) {
                sc[nj][0] = __expf(sc[nj][0] - mn0); sum0 += sc[nj][0];
                sc[nj][1] = __expf(sc[nj][1] - mn0); sum0 += sc[nj][1];
                sc[nj][2] = __expf(sc[nj][2] - mn1); sum1 += sc[nj][2];
                sc[nj][3] = __expf(sc[nj][3] - mn1); sum1 += sc[nj][3];
            }
            l0 = l0 * al0 + sum0;
            l1 = l1 * al1 + sum1;
            #pragma unroll
            for (int nj = 0; nj < 8; nj++) {
                ctx[nj][0] *= al0; ctx[nj][1] *= al0;
                ctx[nj][2] *= al1; ctx[nj][3] *= al1;
            }

            #pragma unroll
            for (int ks = 0; ks < 4; ks++) {
                float* p0 = sc[2 * ks];
                float* p1 = sc[2 * ks + 1];
                uint32_t ph0, ph1, ph2, ph3, pl0, pl1, pl2, pl3;
                PACK_BF16X2(ph0, p0[0], p0[1]);
                PACK_BF16X2(ph1, p0[2], p0[3]);
                PACK_BF16X2(ph2, p1[0], p1[1]);
                PACK_BF16X2(ph3, p1[2], p1[3]);
                {
                    float r00 = p0[0] - __uint_as_float(ph0 << 16);
                    float r01 = p0[1] - __uint_as_float(ph0 & 0xFFFF0000u);
                    float r02 = p0[2] - __uint_as_float(ph1 << 16);
                    float r03 = p0[3] - __uint_as_float(ph1 & 0xFFFF0000u);
                    float r10 = p1[0] - __uint_as_float(ph2 << 16);
                    float r11 = p1[1] - __uint_as_float(ph2 & 0xFFFF0000u);
                    float r12 = p1[2] - __uint_as_float(ph3 << 16);
                    float r13 = p1[3] - __uint_as_float(ph3 & 0xFFFF0000u);
                    PACK_BF16X2(pl0, r00, r01);
                    PACK_BF16X2(pl1, r02, r03);
                    PACK_BF16X2(pl2, r10, r11);
                    PACK_BF16X2(pl3, r12, r13);
                }
                #pragma unroll
                for (int nb = 0; nb < 4; nb++) {
                    uint32_t r0, r1, r2, r3;
                    LDSM_X4_T(r0, r1, r2, r3, vh_s + ks * 2048 + xv[nb]);
                    MMA_BF16(ctx[2*nb][0], ctx[2*nb][1], ctx[2*nb][2], ctx[2*nb][3],
                             ph0, ph1, ph2, ph3, r0, r1);
                    MMA_BF16(ctx[2*nb+1][0], ctx[2*nb+1][1], ctx[2*nb+1][2], ctx[2*nb+1][3],
                             ph0, ph1, ph2, ph3, r2, r3);
                    MMA_BF16(ctx[2*nb][0], ctx[2*nb][1], ctx[2*nb][2], ctx[2*nb][3],
                             pl0, pl1, pl2, pl3, r0, r1);
                    MMA_BF16(ctx[2*nb+1][0], ctx[2*nb+1][1], ctx[2*nb+1][2], ctx[2*nb+1][3],
                             pl0, pl1, pl2, pl3, r2, r3);
                }
                #pragma unroll
                for (int nb = 0; nb < 4; nb++) {
                    uint32_t r0, r1, r2, r3;
                    LDSM_X4_T(r0, r1, r2, r3, vh_s + 8192u + ks * 2048 + xv[nb]);
                    MMA_BF16(ctx[2*nb][0], ctx[2*nb][1], ctx[2*nb][2], ctx[2*nb][3],
                             ph0, ph1, ph2, ph3, r0, r1);
                    MMA_BF16(ctx[2*nb+1][0], ctx[2*nb+1][1], ctx[2*nb+1][2], ctx[2*nb+1][3],
                             ph0, ph1, ph2, ph3, r2, r3);
                }
            }
        }

        MBAR_ARRIVE(mbE + bf * 8);
        if (tid == 0 && kt + 2 < nkt) issueKV(kt + 2, bf);
    }

    l0 += __shfl_xor_sync(0xffffffffu, l0, 1);
    l0 += __shfl_xor_sync(0xffffffffu, l0, 2);
    l1 += __shfl_xor_sync(0xffffffffu, l1, 1);
    l1 += __shfl_xor_sync(0xffffffffu, l1, 2);
    const float inv0 = 1.f / l0, inv1 = 1.f / l1;

    const int grow = b * 2048 + qt * 128 + w * 16 + (lane >> 2);
    const int colb = h * 64 + (lane & 3) * 2;
    #pragma unroll
    for (int nj = 0; nj < 8; nj++) {
        int cc = colb + nj * 8;
        float e0 = ctx[nj][0] * inv0, e1 = ctx[nj][1] * inv0;
        float e2 = ctx[nj][2] * inv1, e3 = ctx[nj][3] * inv1;
        uint32_t hi0, hi1, lo0, lo1;
        PACK_BF16X2(hi0, e0, e1);
        PACK_BF16X2(hi1, e2, e3);
        float h0 = __uint_as_float(hi0 << 16);
        float h1 = __uint_as_float(hi0 & 0xFFFF0000u);
        float h2 = __uint_as_float(hi1 << 16);
        float h3 = __uint_as_float(hi1 & 0xFFFF0000u);
        PACK_BF16X2(lo0, e0 - h0, e1 - h1);
        PACK_BF16X2(lo1, e2 - h2, e3 - h3);
        st_gemm_tile(Cbf, grow,     cc, 0, hi0);
        st_gemm_tile(Cbf, grow,     cc, 1, lo0);
        st_gemm_tile(Cbf, grow + 8, cc, 0, hi1);
        st_gemm_tile(Cbf, grow + 8, cc, 1, lo1);
    }
}

// ---------------------------------------------------------------------------
// Persistent mega-kernel: global work queue over QKV(768) + flash(512) + out(256).
// ---------------------------------------------------------------------------
struct MegaArgs {
    const __nv_bfloat16* A[3];
    const __nv_bfloat16* W[3];
    const float* bias[3];
    __nv_bfloat16* Y[3];
    const __nv_bfloat16* Qbf;
    const __nv_bfloat16* Kbf;
    const __nv_bfloat16* Vbf;
    __nv_bfloat16* Cbf;
    const __nv_bfloat16* Wo;
    const float* bo;
    float* out;
};

__global__ __launch_bounds__(256, 2) void mega_kernel(MegaArgs a)
{
    __shared__ int s_item;
    const int tid = threadIdx.x;

    for (;;) {
        if (tid == 0) s_item = atomicAdd(&g_ctr, 1);
        __syncthreads();
        const int item = s_item;
        __syncthreads();
        if (item >= 1536) return;

        if (item < 768) {
            // QKV tile.  0..255: Q (bm = i>>3, bn = i&7).
            // 256..767: r = i-256; bm = r>>4; sub = r&15; z = 1+(sub&1); bn = sub>>1.
            int z, bm, bn;
            if (item < 256) { z = 0; bm = item >> 3; bn = item & 7; }
            else {
                int r = item - 256;
                bm = r >> 4;
                int sub = r & 15;
                z = 1 + (sub & 1);
                bn = sub >> 1;
            }
            gemm_tile_body<true>(a.A[z], a.W[z], a.bias[z], nullptr, a.Y[z],
                                 D_, bm, bn);
            __threadfence();
            __syncthreads();
            if (tid == 0)
                atomicExch(&g_flag[(z * 32 + bm) * 8 + bn], 1);
        } else if (item < 1280) {
            // Flash tile, heavy-first.
            int j  = item - 768;
            int qt = (S_ / 128 - 1) - (j >> 5);
            int bh = j & 31;
            flash_tile_body(qt, bh >> 4, bh & 15, a.Qbf, a.Kbf, a.Vbf, a.Cbf);
            __threadfence();
            __syncthreads();
            if (tid == 0)
                atomicAdd(&g_cdone[(bh >> 4) * 16 + qt], 1);
        } else {
            // Output tile, qt-descending (chases flash finish order).
            int t  = item - 1280;
            int p  = t >> 4;
            int qt = 15 - p;
            int sub = t & 15;
            int bm = (sub >> 3) * 16 + qt;
            int bn = sub & 7;
            if (tid == 0) {
                while (atomicAdd(&g_cdone[bm], 0) < 16) __nanosleep(128);
                __threadfence();
            }
            __syncthreads();
            gemm_tile_body<false>(a.Cbf, a.Wo, a.bo, a.out, nullptr,
                                  D_, bm, bn);
        }
    }
}

// ---------------------------------------------------------------------------
// Launch
// ---------------------------------------------------------------------------
extern "C" void kernel_launch(void* const* d_in, const int* in_sizes, int n_in,
                              void* d_out, int out_size)
{
    const float* query = (const float*)d_in[0];
    const float* key   = (const float*)d_in[1];
    const float* value = (const float*)d_in[2];
    // d_in[3] = mask — analytically causal (triu k=1).
    const float* Wq = (const float*)d_in[4];
    const float* bq = (const float*)d_in[5];
    const float* Wk = (const float*)d_in[6];
    const float* bk = (const float*)d_in[7];
    const float* Wv = (const float*)d_in[8];
    const float* bv = (const float*)d_in[9];
    const float* Wo = (const float*)d_in[10];
    const float* bo = (const float*)d_in[11];
    float* out = (float*)d_out;

    float* f32 = nullptr;
    __nv_bfloat16* act = nullptr;
    __nv_bfloat16* wbf = nullptr;
    cudaGetSymbolAddress((void**)&f32, g_f32);
    cudaGetSymbolAddress((void**)&act, g_act_bf);
    cudaGetSymbolAddress((void**)&wbf, g_w_bf);

    const size_t TSZ = (size_t)M_ * KP_;
    __nv_bfloat16* pool = (__nv_bfloat16*)f32;
    __nv_bfloat16* Qbf = pool;            // flash-tiled
    __nv_bfloat16* Kbf = pool + TSZ;      // flash-tiled
    __nv_bfloat16* Vbf = pool + 2 * TSZ;  // flash-tiled
    __nv_bfloat16* Cbf = pool + 3 * TSZ;  // gemm-tiled

    __nv_bfloat16* qc = act;              // gemm-tiled
    __nv_bfloat16* kc = act + TSZ;
    __nv_bfloat16* vc = act + 2 * TSZ;
    __nv_bfloat16* wqc = wbf;             // gemm-tiled
    __nv_bfloat16* wkc = wbf + (size_t)D_ * KP_;
    __nv_bfloat16* wvc = wbf + 2 * (size_t)D_ * KP_;
    __nv_bfloat16* woc = wbf + 3 * (size_t)D_ * KP_;

    cudaFuncSetAttribute(mega_kernel,
                         cudaFuncAttributeMaxDynamicSharedMemorySize, SMEM_TOTAL);

    reset_kernel<<<1, 256>>>();

    const int n4_w = D_ * 256;
    const int n4_a = M_ * 256;
    {
        SplitArgs wa;
        wa.X[0] = Wq; wa.X[1] = Wk; wa.X[2] = Wv; wa.X[3] = Wo;
        wa.Y[0] = wqc; wa.Y[1] = wkc; wa.Y[2] = wvc; wa.Y[3] = woc;
        split_bf16_multi<<<dim3((n4_w + 255) / 256, 4), 256>>>(wa, n4_w);
        SplitArgs aa;
        aa.X[0] = query; aa.X[1] = key; aa.X[2] = value; aa.X[3] = query;
        aa.Y[0] = qc; aa.Y[1] = kc; aa.Y[2] = vc; aa.Y[3] = qc;
        split_bf16_multi<<<dim3((n4_a + 255) / 256, 3), 256>>>(aa, n4_a);
    }

    MegaArgs ma;
    ma.A[0] = qc;  ma.A[1] = kc;  ma.A[2] = vc;
    ma.W[0] = wqc; ma.W[1] = wkc; ma.W[2] = wvc;
    ma.bias[0] = bq; ma.bias[1] = bk; ma.bias[2] = bv;
    ma.Y[0] = Qbf; ma.Y[1] = Kbf; ma.Y[2] = Vbf;
    ma.Qbf = Qbf; ma.Kbf = Kbf; ma.Vbf = Vbf; ma.Cbf = Cbf;
    ma.Wo = woc; ma.bo = bo; ma.out = out;

    mega_kernel<<<296, 256, SMEM_TOTAL>>>(ma);
}